// round 16
// baseline (speedup 1.0000x reference)
#include <cuda_runtime.h>
#include <cstdint>

// ---------------------------------------------------------------------------
// QuantumNeuralNetwork: mma.sync bf16-split GEMMs, ldmatrix.trans B operands
//
// <Z0> = e^T M e with M = Re(U' Z0 U) precomputed by build_M_kernel.
//
// R15: occupancy play. 64 samples/block (was 128): smem 55.5KB -> 37KB and
// per-thread regs drop (one m-tile per warp, e[] array removed) ->
// __launch_bounds__(128,6) = 24 warps/SM (occ 37.5%) vs 16. Grid 8192.
// ---------------------------------------------------------------------------

typedef unsigned long long ull;

#define FFMA2(d, a, b) \
    asm("fma.rn.f32x2 %0, %1, %2, %0;" : "+l"(d) : "l"(a), "l"(b))
#define MUL2(d, a, b) \
    asm("mul.rn.f32x2 %0, %1, %2;" : "=l"(d) : "l"(a), "l"(b))
#define ADD2(d, a, b) \
    asm("add.rn.f32x2 %0, %1, %2;" : "=l"(d) : "l"(a), "l"(b))
#define PACK2(out, lo, hi) \
    asm("mov.b64 %0, {%1, %2};" : "=l"(out) : "r"(__float_as_uint(lo)), "r"(__float_as_uint(hi)))
#define UNPACK2(lo, hi, v) do { unsigned _ulo, _uhi; \
    asm("mov.b64 {%0, %1}, %2;" : "=r"(_ulo), "=r"(_uhi) : "l"(v)); \
    lo = __uint_as_float(_ulo); hi = __uint_as_float(_uhi); } while (0)

// ---- smem layout (bytes), 64-sample tiles ----
#define SM_A     0          // image A: 64 rows x 208B (hi 0-95 | lo 96-191 | pad)
#define ASTR     208
#define A_LO     96
#define SM_B     13312      // image B (iW1 [k][n]): 48 rows x 272B (hi | lo at +128)
#define BSTR     272
#define B_LO     128
#define SM_X     26368      // text A: 64 rows x 80B (hi | lo at +32)
#define XSTR     80
#define X_LO     32
#define SM_Y     31488      // text B (tW1 [k][n]): 16 rows x 144B (hi | lo at +64)
#define YSTR     144
#define Y_LO     64
#define SM_TF    0          // alias over A after MMA: [64] float4
#define SM_EP    33792      // epilogue consts (floats)
#define EP_WI2   0          // [64][4]
#define EP_WT2   256        // [32][4]
#define EP_IB1   384        // [64]
#define EP_TB1   448        // [32]
#define EP_B2    480        // [4] ib2+tb2
#define EP_M     484        // [16][16]
#define EP_CLS   740        // cW1[16] cb1[16] cW2[32] cb2[2]
#define EP_FLOATS 808
#define SMEM_BYTES (SM_EP + EP_FLOATS*4)   // 37024

__device__ __forceinline__ uint32_t smem_u32(const void* p) {
    uint32_t a;
    asm("{ .reg .u64 t; cvta.to.shared.u64 t, %1; cvt.u32.u64 %0, t; }" : "=r"(a) : "l"(p));
    return a;
}
__device__ __forceinline__ unsigned bf16pair(float lo, float hi) {
    unsigned r; asm("cvt.rn.bf16x2.f32 %0, %1, %2;" : "=r"(r) : "f"(hi), "f"(lo)); return r;
}
__device__ __forceinline__ void ldsm_x4(unsigned* r, uint32_t addr) {
    asm volatile("ldmatrix.sync.aligned.m8n8.x4.shared.b16 {%0,%1,%2,%3}, [%4];"
        : "=r"(r[0]), "=r"(r[1]), "=r"(r[2]), "=r"(r[3]) : "r"(addr));
}
__device__ __forceinline__ void ldsm_x2t(unsigned* r, uint32_t addr) {
    asm volatile("ldmatrix.sync.aligned.m8n8.x2.trans.shared.b16 {%0,%1}, [%2];"
        : "=r"(r[0]), "=r"(r[1]) : "r"(addr));
}
__device__ __forceinline__ void mma_bf16(float* d, const unsigned* a, const unsigned* b) {
    asm volatile("mma.sync.aligned.m16n8k16.row.col.f32.bf16.bf16.f32 "
        "{%0,%1,%2,%3}, {%4,%5,%6,%7}, {%8,%9}, {%0,%1,%2,%3};"
        : "+f"(d[0]), "+f"(d[1]), "+f"(d[2]), "+f"(d[3])
        : "r"(a[0]), "r"(a[1]), "r"(a[2]), "r"(a[3]), "r"(b[0]), "r"(b[1]));
}

__device__ __align__(16) float g_M[256];

// ---------------------------------------------------------------------------
// Prologue: build M[16][16] = Re(U^dagger Z0 U) from qweights [2][4][3].
// ---------------------------------------------------------------------------
__global__ void build_M_kernel(const float* __restrict__ qw) {
    __shared__ float Ure[16][16], Uim[16][16];
    const int k = threadIdx.x;
    float vr[16], vi[16];
#pragma unroll
    for (int n = 0; n < 16; n++) { vr[n] = (n == k) ? 1.f : 0.f; vi[n] = 0.f; }

    for (int l = 0; l < 2; l++) {
        for (int i = 0; i < 4; i++) {
            float phi = qw[(l*4 + i)*3 + 0];
            float th  = qw[(l*4 + i)*3 + 1];
            float om  = qw[(l*4 + i)*3 + 2];
            float ct = cosf(0.5f*th), st = sinf(0.5f*th);
            float sp, cp, sm, cm;
            sincosf(0.5f*(phi + om), &sp, &cp);
            sincosf(0.5f*(phi - om), &sm, &cm);
            float u00r =  cp*ct, u00i = -sp*ct;
            float u01r = -cm*st, u01i = -sm*st;
            float u10r =  cm*st, u10i = -sm*st;
            float u11r =  cp*ct, u11i =  sp*ct;
            int mask = 1 << (3 - i);
#pragma unroll
            for (int n = 0; n < 16; n++) {
                if (n & mask) continue;
                int n1 = n | mask;
                float r0 = vr[n],  i0 = vi[n];
                float r1 = vr[n1], i1 = vi[n1];
                vr[n]  = u00r*r0 - u00i*i0 + u01r*r1 - u01i*i1;
                vi[n]  = u00r*i0 + u00i*r0 + u01r*i1 + u01i*r1;
                vr[n1] = u10r*r0 - u10i*i0 + u11r*r1 - u11i*i1;
                vi[n1] = u10r*i0 + u10i*r0 + u11r*i1 + u11i*r1;
            }
        }
        for (int i = 0; i < 3; i++) {
            int m1 = 1 << (3 - i), m2 = 1 << (2 - i);
#pragma unroll
            for (int n = 0; n < 16; n++)
                if ((n & m1) && (n & m2)) { vr[n] = -vr[n]; vi[n] = -vi[n]; }
        }
    }
#pragma unroll
    for (int n = 0; n < 16; n++) { Ure[n][k] = vr[n]; Uim[n][k] = vi[n]; }
    __syncthreads();
#pragma unroll
    for (int j = 0; j < 16; j++) {
        float acc = 0.f;
#pragma unroll
        for (int b = 0; b < 16; b++) {
            float z = (b & 8) ? -1.f : 1.f;
            acc += z * (Ure[b][j]*Ure[b][k] + Uim[b][j]*Uim[b][k]);
        }
        g_M[j*16 + k] = acc;
    }
}

// ---------------------------------------------------------------------------
// Main kernel: 128 threads, 64 samples per block. Warp w owns rows 16w..16w+15.
// ---------------------------------------------------------------------------
__global__ __launch_bounds__(128, 6) void qnn_kernel(
    const float* __restrict__ text, const float* __restrict__ image,
    const float* __restrict__ tW1,  const float* __restrict__ tb1,
    const float* __restrict__ tW2,  const float* __restrict__ tb2,
    const float* __restrict__ iW1,  const float* __restrict__ ib1,
    const float* __restrict__ iW2,  const float* __restrict__ ib2,
    const float* __restrict__ cW1,  const float* __restrict__ cb1,
    const float* __restrict__ cW2,  const float* __restrict__ cb2,
    float* __restrict__ out)
{
    extern __shared__ __align__(1024) char smc[];
    const uint32_t smem_base = smem_u32(smc);
    float* ep = (float*)(smc + SM_EP);

    const int tid = threadIdx.x;
    const int w   = tid >> 5;
    const int l   = tid & 31;
    const size_t base = (size_t)blockIdx.x * 64;

    // ---- stage: convert inputs/weights to bf16 hi/lo tiles ----
    {
        // image A [64][48] -> A tile, stride 208B
        const float4* ig = (const float4*)(image + base * 48);
#pragma unroll
        for (int it = 0; it < 6; it++) {
            int idx = it*128 + tid;
            float4 v = ig[idx];
            int s  = idx / 12;
            int kq = idx - s*12;
            unsigned off = (unsigned)s*ASTR + 8u*kq;
            unsigned hp0 = bf16pair(v.x, v.y);
            unsigned hp1 = bf16pair(v.z, v.w);
            float r0 = v.x - __uint_as_float(hp0 << 16);
            float r1 = v.y - __uint_as_float(hp0 & 0xffff0000u);
            float r2 = v.z - __uint_as_float(hp1 << 16);
            float r3 = v.w - __uint_as_float(hp1 & 0xffff0000u);
            unsigned lp0 = bf16pair(r0, r1);
            unsigned lp1 = bf16pair(r2, r3);
            *(ull*)(smc + SM_A + off)        = (ull)hp0 | ((ull)hp1 << 32);
            *(ull*)(smc + SM_A + A_LO + off) = (ull)lp0 | ((ull)lp1 << 32);
        }
        // image B: iW1[48][64] kept [k][n]
#pragma unroll
        for (int it = 0; it < 6; it++) {
            int idx = it*128 + tid;
            float4 v = ((const float4*)iW1)[idx];
            int kk = idx >> 4;
            int n0 = (idx & 15) * 4;
            unsigned off = (unsigned)kk*BSTR + 2u*n0;
            unsigned hp0 = bf16pair(v.x, v.y);
            unsigned hp1 = bf16pair(v.z, v.w);
            float r0 = v.x - __uint_as_float(hp0 << 16);
            float r1 = v.y - __uint_as_float(hp0 & 0xffff0000u);
            float r2 = v.z - __uint_as_float(hp1 << 16);
            float r3 = v.w - __uint_as_float(hp1 & 0xffff0000u);
            unsigned lp0 = bf16pair(r0, r1);
            unsigned lp1 = bf16pair(r2, r3);
            *(ull*)(smc + SM_B + off)        = (ull)hp0 | ((ull)hp1 << 32);
            *(ull*)(smc + SM_B + B_LO + off) = (ull)lp0 | ((ull)lp1 << 32);
        }
        // text A [64][16] -> X tile, stride 80B
        const float4* tg = (const float4*)(text + base * 16);
#pragma unroll
        for (int it = 0; it < 2; it++) {
            int idx = it*128 + tid;
            float4 v = tg[idx];
            int s  = idx >> 2;
            int kq = idx & 3;
            unsigned off = (unsigned)s*XSTR + 8u*kq;
            unsigned hp0 = bf16pair(v.x, v.y);
            unsigned hp1 = bf16pair(v.z, v.w);
            float r0 = v.x - __uint_as_float(hp0 << 16);
            float r1 = v.y - __uint_as_float(hp0 & 0xffff0000u);
            float r2 = v.z - __uint_as_float(hp1 << 16);
            float r3 = v.w - __uint_as_float(hp1 & 0xffff0000u);
            unsigned lp0 = bf16pair(r0, r1);
            unsigned lp1 = bf16pair(r2, r3);
            *(ull*)(smc + SM_X + off)        = (ull)hp0 | ((ull)hp1 << 32);
            *(ull*)(smc + SM_X + X_LO + off) = (ull)lp0 | ((ull)lp1 << 32);
        }
        // text B: tW1[16][32] kept [k][n], stride 144B
        {
            int idx = tid;
            float4 v = ((const float4*)tW1)[idx];
            int kk = idx >> 3;
            int n0 = (idx & 7) * 4;
            unsigned off = (unsigned)kk*YSTR + 2u*n0;
            unsigned hp0 = bf16pair(v.x, v.y);
            unsigned hp1 = bf16pair(v.z, v.w);
            float r0 = v.x - __uint_as_float(hp0 << 16);
            float r1 = v.y - __uint_as_float(hp0 & 0xffff0000u);
            float r2 = v.z - __uint_as_float(hp1 << 16);
            float r3 = v.w - __uint_as_float(hp1 & 0xffff0000u);
            unsigned lp0 = bf16pair(r0, r1);
            unsigned lp1 = bf16pair(r2, r3);
            *(ull*)(smc + SM_Y + off)        = (ull)hp0 | ((ull)hp1 << 32);
            *(ull*)(smc + SM_Y + Y_LO + off) = (ull)lp0 | ((ull)lp1 << 32);
        }
        // epilogue constants
        if (tid < 64) {
            ((float4*)(ep + EP_WI2))[tid] = ((const float4*)iW2)[tid];
            ep[EP_IB1 + tid] = ib1[tid];
            ((float4*)(ep + EP_M))[tid] = ((const float4*)g_M)[tid];
        }
        if (tid < 32) {
            ((float4*)(ep + EP_WT2))[tid] = ((const float4*)tW2)[tid];
            ep[EP_TB1 + tid] = tb1[tid];
        }
        if (tid < 16) {
            ep[EP_CLS + tid] = cW1[tid];
            ep[EP_CLS + 16 + tid] = cb1[tid];
            ep[EP_CLS + 32 + 2*tid] = cW2[2*tid];
            ep[EP_CLS + 33 + 2*tid] = cW2[2*tid + 1];
        }
        if (tid < 4) ep[EP_B2 + tid] = ib2[tid] + tb2[tid];
        if (tid < 2) ep[EP_CLS + 64 + tid] = cb2[tid];
    }
    __syncthreads();

    const unsigned aRow = 16u*w + (l & 15);
    const unsigned aCol = (unsigned)(l >> 4) * 16u;
    const unsigned bKl  = (unsigned)(l & 15);          // k row for trans B loads

    ull pvA[2], pvB[2];
    pvA[0] = pvA[1] = pvB[0] = pvB[1] = 0ull;

    // ---- image GEMM (mma.sync, 3-term bf16 split) + in-register fold ----
    {
        float D[8][4];
#pragma unroll
        for (int nt = 0; nt < 8; nt++)
#pragma unroll
            for (int c = 0; c < 4; c++) D[nt][c] = 0.f;

#pragma unroll
        for (int kc = 0; kc < 3; kc++) {
            unsigned kB = kc * 32u;
            uint32_t bRowAddr = smem_base + SM_B + (kc*16u + bKl)*BSTR;
            unsigned ah[4], al[4], bh[8][2], bl[8][2];
            ldsm_x4(ah, smem_base + SM_A + aRow*ASTR + kB + aCol);
#pragma unroll
            for (int nt = 0; nt < 8; nt++)
                ldsm_x2t(bh[nt], bRowAddr + nt*16u);
#pragma unroll
            for (int nt = 0; nt < 8; nt++) mma_bf16(D[nt], ah, bh[nt]);
#pragma unroll
            for (int nt = 0; nt < 8; nt++)
                ldsm_x2t(bl[nt], bRowAddr + B_LO + nt*16u);
#pragma unroll
            for (int nt = 0; nt < 8; nt++) mma_bf16(D[nt], ah, bl[nt]);
            ldsm_x4(al, smem_base + SM_A + A_LO + aRow*ASTR + kB + aCol);
#pragma unroll
            for (int nt = 0; nt < 8; nt++) mma_bf16(D[nt], al, bh[nt]);
        }

        const float* wI2s = ep + EP_WI2;
        const float* ib1s = ep + EP_IB1;
#pragma unroll
        for (int nt = 0; nt < 8; nt++) {
            int c0 = 8*nt + 2*(l & 3);
            ulonglong2 w0 = *(const ulonglong2*)&wI2s[c0*4];
            ulonglong2 w1 = *(const ulonglong2*)&wI2s[(c0+1)*4];
            float b0 = ib1s[c0], b1 = ib1s[c0+1];
#pragma unroll
            for (int bb = 0; bb < 2; bb++) {
                float h0 = fmaxf(D[nt][2*bb]   + b0, 0.f);
                float h1 = fmaxf(D[nt][2*bb+1] + b1, 0.f);
                ull hh0, hh1; PACK2(hh0, h0, h0); PACK2(hh1, h1, h1);
                FFMA2(pvA[bb], hh0, w0.x); FFMA2(pvB[bb], hh0, w0.y);
                FFMA2(pvA[bb], hh1, w1.x); FFMA2(pvB[bb], hh1, w1.y);
            }
        }
    }

    // ---- text GEMM (mma.sync, 3-term, single k-chunk) + fold into same pv ----
    {
        float Dt[4][4];
#pragma unroll
        for (int nt = 0; nt < 4; nt++)
#pragma unroll
            for (int c = 0; c < 4; c++) Dt[nt][c] = 0.f;

        uint32_t yRowAddr = smem_base + SM_Y + bKl*YSTR;
        unsigned xh[4], xl[4], yh[4][2], yl[4][2];
        ldsm_x4(xh, smem_base + SM_X + aRow*XSTR + aCol);
#pragma unroll
        for (int nt = 0; nt < 4; nt++)
            ldsm_x2t(yh[nt], yRowAddr + nt*16u);
#pragma unroll
        for (int nt = 0; nt < 4; nt++) mma_bf16(Dt[nt], xh, yh[nt]);
#pragma unroll
        for (int nt = 0; nt < 4; nt++)
            ldsm_x2t(yl[nt], yRowAddr + Y_LO + nt*16u);
#pragma unroll
        for (int nt = 0; nt < 4; nt++) mma_bf16(Dt[nt], xh, yl[nt]);
        ldsm_x4(xl, smem_base + SM_X + X_LO + aRow*XSTR + aCol);
#pragma unroll
        for (int nt = 0; nt < 4; nt++) mma_bf16(Dt[nt], xl, yh[nt]);

        const float* wT2s = ep + EP_WT2;
        const float* tb1s = ep + EP_TB1;
#pragma unroll
        for (int nt = 0; nt < 4; nt++) {
            int c0 = 8*nt + 2*(l & 3);
            ulonglong2 w0 = *(const ulonglong2*)&wT2s[c0*4];
            ulonglong2 w1 = *(const ulonglong2*)&wT2s[(c0+1)*4];
            float b0 = tb1s[c0], b1 = tb1s[c0+1];
#pragma unroll
            for (int bb = 0; bb < 2; bb++) {
                float h0 = fmaxf(Dt[nt][2*bb]   + b0, 0.f);
                float h1 = fmaxf(Dt[nt][2*bb+1] + b1, 0.f);
                ull hh0, hh1; PACK2(hh0, h0, h0); PACK2(hh1, h1, h1);
                FFMA2(pvA[bb], hh0, w0.x); FFMA2(pvB[bb], hh0, w0.y);
                FFMA2(pvA[bb], hh1, w1.x); FFMA2(pvB[bb], hh1, w1.y);
            }
        }
    }

    // ---- quad-shfl reduce (cols live in lanes l^1, l^2 of each quad) ----
#pragma unroll
    for (int s = 0; s < 2; s++) {
        ull t;
        t = __shfl_xor_sync(0xffffffffu, pvA[s], 1); ADD2(pvA[s], pvA[s], t);
        t = __shfl_xor_sync(0xffffffffu, pvA[s], 2); ADD2(pvA[s], pvA[s], t);
        t = __shfl_xor_sync(0xffffffffu, pvB[s], 1); ADD2(pvB[s], pvB[s], t);
        t = __shfl_xor_sync(0xffffffffu, pvB[s], 2); ADD2(pvB[s], pvB[s], t);
    }

    __syncthreads();   // all mma reads done -> TF buffer may alias A

    if ((l & 3) == 0) {
#pragma unroll
        for (int s = 0; s < 2; s++) {
            int row = 16*w + 8*s + (l >> 2);
            ulonglong2 v; v.x = pvA[s]; v.y = pvB[s];
            *(ulonglong2*)(smc + SM_TF + row*16) = v;
        }
    }
    __syncthreads();

    // ---- feats + quantum + classifier: one sample per thread (tid < 64) ----
    if (tid < 64) {
        float fx, fy, fz, fw;
        {
            ulonglong2 ti = *(const ulonglong2*)(smc + SM_TF + tid*16);
            ulonglong2 bb = *(const ulonglong2*)(ep + EP_B2);
            ull half2p; PACK2(half2p, 0.5f, 0.5f);
            ull sA, sB;
            ADD2(sA, ti.x, bb.x); MUL2(sA, sA, half2p);
            ADD2(sB, ti.y, bb.y); MUL2(sB, sB, half2p);
            UNPACK2(fx, fy, sA); UNPACK2(fz, fw, sB);
        }

        const float* Ms  = ep + EP_M;
        const float* cls = ep + EP_CLS;
        float c0, q0s, c1, q1s, c2, q2s, c3, q3s;
        __sincosf(0.5f*fx, &q0s, &c0);
        __sincosf(0.5f*fy, &q1s, &c1);
        __sincosf(0.5f*fz, &q2s, &c2);
        __sincosf(0.5f*fw, &q3s, &c3);

        float p01[4] = {c0*c1, c0*q1s, q0s*c1, q0s*q1s};
        float p23[4] = {c2*c3, c2*q3s, q2s*c3, q2s*q3s};
        ull p23p0, p23p1;
        PACK2(p23p0, p23[0], p23[1]);
        PACK2(p23p1, p23[2], p23[3]);
        ull e2[8];
#pragma unroll
        for (int a = 0; a < 4; a++) {
            ull pa; PACK2(pa, p01[a], p01[a]);
            MUL2(e2[a*2+0], pa, p23p0);
            MUL2(e2[a*2+1], pa, p23p1);
        }

        float q = 0.f;
#pragma unroll
        for (int j = 0; j < 8; j++) {   // pairs of rows 2j, 2j+1
            ull t2a = 0ull, t2b = 0ull;
            const ulonglong2* Mr0 = (const ulonglong2*)&Ms[(2*j)*16];
            const ulonglong2* Mr1 = (const ulonglong2*)&Ms[(2*j+1)*16];
#pragma unroll
            for (int h = 0; h < 4; h++) {
                ulonglong2 ma = Mr0[h], mb = Mr1[h];
                FFMA2(t2a, ma.x, e2[2*h]); FFMA2(t2a, ma.y, e2[2*h+1]);
                FFMA2(t2b, mb.x, e2[2*h]); FFMA2(t2b, mb.y, e2[2*h+1]);
            }
            float ej0, ej1; UNPACK2(ej0, ej1, e2[j]);
            float ta0, ta1; UNPACK2(ta0, ta1, t2a);
            float tb0, tb1; UNPACK2(tb0, tb1, t2b);
            q = fmaf(ej0, ta0 + ta1, q);
            q = fmaf(ej1, tb0 + tb1, q);
        }

        float o0 = cls[64], o1 = cls[65];
#pragma unroll
        for (int m = 0; m < 16; m++) {
            float h = fmaxf(fmaf(q, cls[m], cls[16+m]), 0.f);
            o0 = fmaf(h, cls[32+2*m], o0);
            o1 = fmaf(h, cls[33+2*m], o1);
        }
        float2 res; res.x = o0; res.y = o1;
        ((float2*)out)[base + tid] = res;
    }
}

// ---------------------------------------------------------------------------
extern "C" void kernel_launch(void* const* d_in, const int* in_sizes, int n_in,
                              void* d_out, int out_size) {
    const float* text = (const float*)d_in[0];
    const float* image= (const float*)d_in[1];
    const float* tW1  = (const float*)d_in[2];
    const float* tb1  = (const float*)d_in[3];
    const float* tW2  = (const float*)d_in[4];
    const float* tb2  = (const float*)d_in[5];
    const float* iW1  = (const float*)d_in[6];
    const float* ib1  = (const float*)d_in[7];
    const float* iW2  = (const float*)d_in[8];
    const float* ib2  = (const float*)d_in[9];
    const float* qw   = (const float*)d_in[10];
    const float* cW1  = (const float*)d_in[11];
    const float* cb1  = (const float*)d_in[12];
    const float* cW2  = (const float*)d_in[13];
    const float* cb2  = (const float*)d_in[14];
    float* out = (float*)d_out;

    const int B = in_sizes[0] / 16;
    const int grid = B / 64;

    cudaFuncSetAttribute(qnn_kernel, cudaFuncAttributeMaxDynamicSharedMemorySize, SMEM_BYTES);

    build_M_kernel<<<1, 16>>>(qw);
    qnn_kernel<<<grid, 128, SMEM_BYTES>>>(text, image, tW1, tb1, tW2, tb2,
                                          iW1, ib1, iW2, ib2,
                                          cW1, cb1, cW2, cb2, out);
}